// round 4
// baseline (speedup 1.0000x reference)
#include <cuda_runtime.h>
#include <cuda_bf16.h>

#define NMAX 100000
#define DH   64
#define GMAX 64
#define DOUT 32
#define BMAX 65   // <= 64 thresholds -> <= 65 buckets

// ---- scratch ---------------------------------------------------------------
__device__ __align__(256) float2 d_pq[(size_t)BMAX * NMAX];  // (p,q), [b][i]
__device__ __align__(256) float4 d_ninfo[NMAX];              // (a=dinv*c, dinv, bits(b), 0)
__device__ float d_S[NMAX];          // S, then reused as c
__device__ float d_dinv[NMAX];
__device__ int   d_deg[NMAX];
__device__ float d_u[BMAX * DH];     // (v .* mask_b) @ W2
__device__ float d_w[BMAX * DH];     // (b1 .* mask_b) @ W2
__device__ float d_tsort[DH];
__device__ int   d_Beff;
__device__ unsigned d_cminb, d_cmaxb;
__device__ int   d_gstart[GMAX + 2];
__device__ float d_pooled[GMAX * DH];
__device__ int   d_ctr1, d_ctr2;

// 0) zero deg, S, pooled, min/max, counters
__global__ __launch_bounds__(256) void k_init(int N) {
    int i = blockIdx.x * blockDim.x + threadIdx.x;
    if (i < N) { d_deg[i] = 0; d_S[i] = 0.f; }
    if (i < GMAX * DH) d_pooled[i] = 0.f;
    if (i == 0) { d_cminb = 0x7f800000u; d_cmaxb = 0u; d_ctr1 = 0; d_ctr2 = 0; }
}

// 1) in-degree on dst (4 edges/thread, int4 loads)
__global__ __launch_bounds__(256) void k_deg(const int* __restrict__ ei, int E) {
    int t = blockIdx.x * blockDim.x + threadIdx.x;
    int e = t * 4;
    if (e + 3 < E) {
        int4 d4 = *(const int4*)&ei[E + e];
        atomicAdd(&d_deg[d4.x], 1);
        atomicAdd(&d_deg[d4.y], 1);
        atomicAdd(&d_deg[d4.z], 1);
        atomicAdd(&d_deg[d4.w], 1);
    } else {
        for (int k = e; k < E; k++) atomicAdd(&d_deg[ei[E + k]], 1);
    }
}

// 2) S[dst] += rsqrt(deg[src]+1)  (2 edges/thread)
__global__ __launch_bounds__(256) void k_S(const int* __restrict__ ei, int E) {
    int t = blockIdx.x * blockDim.x + threadIdx.x;
    int e = t * 2;
    if (e + 1 < E) {
        int2 s2 = *(const int2*)&ei[e];
        int2 d2 = *(const int2*)&ei[E + e];
        atomicAdd(&d_S[d2.x], rsqrtf((float)d_deg[s2.x] + 1.0f));
        atomicAdd(&d_S[d2.y], rsqrtf((float)d_deg[s2.y] + 1.0f));
    } else if (e < E) {
        atomicAdd(&d_S[ei[E + e]], rsqrtf((float)d_deg[ei[e]] + 1.0f));
    }
}

// 3) per node: dinv, c; global min/max; LAST BLOCK builds threshold tables
__global__ __launch_bounds__(256) void k_c_thresh(const float* __restrict__ emb,
                                                  const float* __restrict__ W1,
                                                  const float* __restrict__ b1,
                                                  const float* __restrict__ W2, int N) {
    int i = blockIdx.x * blockDim.x + threadIdx.x;
    bool valid = (i < N);
    float dv = 0.f, c = 0.f;
    if (valid) {
        dv = rsqrtf((float)d_deg[i] + 1.0f);
        c  = dv * (d_S[i] + dv);
        d_dinv[i] = dv; d_S[i] = c;
    }
    unsigned cb = __float_as_uint(c);
    unsigned mn = __reduce_min_sync(0xffffffffu, valid ? cb : 0x7f800000u);
    unsigned mx = __reduce_max_sync(0xffffffffu, valid ? cb : 0u);
    if ((threadIdx.x & 31) == 0) {
        atomicMin(&d_cminb, mn);
        atomicMax(&d_cmaxb, mx);
    }
    __threadfence();
    __shared__ int isLast;
    __syncthreads();
    if (threadIdx.x == 0)
        isLast = (atomicAdd(&d_ctr1, 1) == (int)gridDim.x - 1);
    __syncthreads();
    if (!isLast) return;

    // ---- threshold phase (single surviving block) ----
    __shared__ float sv[DH], sb1[DH], st[DH], ssort[DH];
    __shared__ int sinr[DH], scnt;
    int t = threadIdx.x;
    if (t < DH) {
        float a = 0.f;
        #pragma unroll
        for (int k = 0; k < DH; k++) a = fmaf(emb[k], W1[k * DH + t], a);
        sv[t] = a; sb1[t] = b1[t];
    }
    __syncthreads();
    float cmin = __uint_as_float(d_cminb);
    float cmax = __uint_as_float(d_cmaxb);
    if (t < DH) {
        float vv = sv[t];
        float th = -sb1[t] / vv;                   // NaN/inf auto-fail range test
        int inr = (vv != 0.f) && (th > cmin) && (th < cmax);
        st[t] = th; sinr[t] = inr;
    }
    __syncthreads();
    if (t < DH && sinr[t]) {
        float th = st[t]; int r = 0;
        for (int d = 0; d < DH; d++)
            if (sinr[d] && (st[d] < th || (st[d] == th && d < t))) r++;
        ssort[r] = th;
    }
    if (t == 0) {
        int cc = 0;
        for (int d = 0; d < DH; d++) cc += sinr[d];
        scnt = cc; d_Beff = cc + 1;
    }
    __syncthreads();
    int cnt = scnt;
    if (t < cnt) d_tsort[t] = ssort[t];
    for (int task = t; task < BMAX * DH; task += 256) {
        int b = task >> 6, j = task & 63;
        if (b > cnt) continue;
        float lo = (b == 0)   ? cmin : ssort[b - 1];
        float hi = (b == cnt) ? cmax : ssort[b];
        float rep = 0.5f * (lo + hi);
        float uu = 0.f, ww = 0.f;
        for (int d = 0; d < DH; d++) {
            if (fmaf(rep, sv[d], sb1[d]) > 0.f) {
                float wdj = W2[d * DH + j];
                uu = fmaf(sv[d], wdj, uu);
                ww = fmaf(sb1[d], wdj, ww);
            }
        }
        d_u[b * DH + j] = uu;
        d_w[b * DH + j] = ww;
    }
}

// 4) per node: bucket id + ninfo + graph bounds + zero pq rows [0,Beff)
__global__ __launch_bounds__(256) void k_bucket(const int* __restrict__ batch,
                                                int N, int G) {
    __shared__ float ts[DH];
    __shared__ int sBeff;
    if (threadIdx.x == 0) sBeff = d_Beff;
    if (threadIdx.x < DH) ts[threadIdx.x] = d_tsort[threadIdx.x];
    __syncthreads();
    int i = blockIdx.x * blockDim.x + threadIdx.x;
    int Beff = sBeff;
    int cnt = Beff - 1;
    if (i < N) {
        float c = d_S[i];
        float dv = d_dinv[i];
        int b = 0;
        for (int k = 0; k < cnt; k++) b += (ts[k] < c);
        d_ninfo[i] = make_float4(dv * c, dv, __int_as_float(b), 0.f);
        float2 z = make_float2(0.f, 0.f);
        for (int b2 = 0; b2 < Beff; b2++)
            d_pq[(size_t)b2 * N + i] = z;          // coalesced per-b2 row
    }
    if (i <= N) {
        int cur  = (i < N) ? batch[i] : G;
        int prev = (i == 0) ? -1 : batch[i - 1];
        for (int g = prev + 1; g <= cur; g++) d_gstart[g] = i;
    }
}

// 5) edge aggregation: 8-byte float2 RED per edge (2 edges/thread)
__global__ __launch_bounds__(256) void k_edge(const int* __restrict__ ei, int E, int N) {
    int t = blockIdx.x * blockDim.x + threadIdx.x;
    int e = t * 2;
    if (e + 1 < E) {
        int2 s2 = *(const int2*)&ei[e];
        int2 d2 = *(const int2*)&ei[E + e];
        float4 n0 = d_ninfo[s2.x];
        float4 n1 = d_ninfo[s2.y];
        atomicAdd(&d_pq[(size_t)__float_as_int(n0.z) * N + d2.x], make_float2(n0.x, n0.y));
        atomicAdd(&d_pq[(size_t)__float_as_int(n1.z) * N + d2.y], make_float2(n1.x, n1.y));
    } else if (e < E) {
        int s = ei[e], d = ei[E + e];
        float4 ni = d_ninfo[s];
        atomicAdd(&d_pq[(size_t)__float_as_int(ni.z) * N + d], make_float2(ni.x, ni.y));
    }
}

// 6) per node: h2 = relu(dinv*(self + sum_b p*u_b+q*w_b) + b2); fused mean-pool;
//    LAST BLOCK does mean + FC for all graphs.
__global__ __launch_bounds__(256) void k_out(const int* __restrict__ batch,
                                             const float* __restrict__ b2,
                                             const float* __restrict__ fcW,
                                             const float* __restrict__ fcb,
                                             float* __restrict__ out, int N, int G) {
    __shared__ float su[BMAX * DH];
    __shared__ float sw[BMAX * DH];
    __shared__ float swarp[8][DH];
    __shared__ float sb2[DH];
    __shared__ int sg0;
    int t = threadIdx.x;
    int Beff = d_Beff;
    for (int k = t; k < Beff * DH; k += 256) { su[k] = d_u[k]; sw[k] = d_w[k]; }
    if (t < DH) sb2[t] = b2[t];
    int i0 = blockIdx.x * 64;
    if (t == 0) sg0 = (i0 < N) ? batch[i0] : 0;
    __syncthreads();

    int node = i0 + (t >> 2);
    int part = t & 3;
    int g0 = sg0;

    float acc[16];
    #pragma unroll
    for (int k = 0; k < 16; k++) acc[k] = 0.f;
    float dv = 0.f;
    int g = g0;
    if (node < N) {
        float4 ni = d_ninfo[node];
        dv = ni.y;
        g = batch[node];
        // self-loop term
        {
            int bi = __float_as_int(ni.z);
            const float4* u4 = (const float4*)&su[bi * DH + part * 16];
            const float4* w4 = (const float4*)&sw[bi * DH + part * 16];
            #pragma unroll
            for (int jj = 0; jj < 4; jj++) {
                float4 u = u4[jj], w = w4[jj];
                acc[jj * 4 + 0] = fmaf(ni.x, u.x, dv * w.x);
                acc[jj * 4 + 1] = fmaf(ni.x, u.y, dv * w.y);
                acc[jj * 4 + 2] = fmaf(ni.x, u.z, dv * w.z);
                acc[jj * 4 + 3] = fmaf(ni.x, u.w, dv * w.w);
            }
        }
        for (int b = 0; b < Beff; b++) {
            float2 pq = d_pq[(size_t)b * N + node];
            if (pq.y != 0.f) {
                const float4* u4 = (const float4*)&su[b * DH + part * 16];
                const float4* w4 = (const float4*)&sw[b * DH + part * 16];
                #pragma unroll
                for (int jj = 0; jj < 4; jj++) {
                    float4 u = u4[jj], w = w4[jj];
                    acc[jj * 4 + 0] = fmaf(pq.x, u.x, fmaf(pq.y, w.x, acc[jj * 4 + 0]));
                    acc[jj * 4 + 1] = fmaf(pq.x, u.y, fmaf(pq.y, w.y, acc[jj * 4 + 1]));
                    acc[jj * 4 + 2] = fmaf(pq.x, u.z, fmaf(pq.y, w.z, acc[jj * 4 + 2]));
                    acc[jj * 4 + 3] = fmaf(pq.x, u.w, fmaf(pq.y, w.w, acc[jj * 4 + 3]));
                }
            }
        }
    }
    float h[16];
    #pragma unroll
    for (int k = 0; k < 16; k++)
        h[k] = (node < N) ? fmaxf(fmaf(dv, acc[k], sb2[part * 16 + k]), 0.f) : 0.f;

    if (node < N && g != g0) {                     // graph-boundary stray
        #pragma unroll
        for (int k = 0; k < 16; k++)
            atomicAdd(&d_pooled[g * DH + part * 16 + k], h[k]);
        #pragma unroll
        for (int k = 0; k < 16; k++) h[k] = 0.f;
    }
    #pragma unroll
    for (int k = 0; k < 16; k++) {
        h[k] += __shfl_xor_sync(0xffffffffu, h[k], 16);
        h[k] += __shfl_xor_sync(0xffffffffu, h[k], 8);
        h[k] += __shfl_xor_sync(0xffffffffu, h[k], 4);
    }
    int lane = t & 31, warp = t >> 5;
    if (lane < 4) {
        #pragma unroll
        for (int k = 0; k < 16; k++) swarp[warp][lane * 16 + k] = h[k];
    }
    __syncthreads();
    if (t < DH) {
        float tot = 0.f;
        #pragma unroll
        for (int wq = 0; wq < 8; wq++) tot += swarp[wq][t];
        atomicAdd(&d_pooled[g0 * DH + t], tot);
    }

    // ---- last block: mean + FC for all graphs ----
    __threadfence();
    __shared__ int isLast;
    __syncthreads();
    if (t == 0) isLast = (atomicAdd(&d_ctr2, 1) == (int)gridDim.x - 1);
    __syncthreads();
    if (!isLast) return;
    __shared__ float sfw[DH * DOUT];
    for (int k = t; k < DH * DOUT; k += 256) sfw[k] = fcW[k];
    __syncthreads();
    for (int idx = t; idx < G * DOUT; idx += 256) {
        int gg = idx >> 5, o = idx & 31;
        float cntf = (float)(d_gstart[gg + 1] - d_gstart[gg]);
        float inv = 1.f / fmaxf(cntf, 1.f);
        float r = fcb[o];
        #pragma unroll
        for (int f = 0; f < DH; f++)
            r = fmaf(d_pooled[gg * DH + f] * inv, sfw[f * DOUT + o], r);
        out[idx] = r;
    }
}

extern "C" void kernel_launch(void* const* d_in, const int* in_sizes, int n_in,
                              void* d_out, int out_size) {
    // metadata order: x, edge_index, batch, emb, W1, b1, W2, b2, fcW, fcb
    const int*   ei    = (const int*)d_in[1];
    const int*   batch = (const int*)d_in[2];
    const float* emb   = (const float*)d_in[3];
    const float* W1    = (const float*)d_in[4];
    const float* b1    = (const float*)d_in[5];
    const float* W2    = (const float*)d_in[6];
    const float* b2    = (const float*)d_in[7];
    const float* fcW   = (const float*)d_in[8];
    const float* fcb   = (const float*)d_in[9];
    float* out = (float*)d_out;

    int N = in_sizes[0];
    int E = in_sizes[1] / 2;
    int G = out_size / DOUT;

    const int tb = 256;
    k_init<<<(N + tb - 1) / tb, tb>>>(N);
    k_deg<<<((E + 3) / 4 + tb - 1) / tb, tb>>>(ei, E);
    k_S<<<((E + 1) / 2 + tb - 1) / tb, tb>>>(ei, E);
    k_c_thresh<<<(N + tb - 1) / tb, tb>>>(emb, W1, b1, W2, N);
    k_bucket<<<(N + 1 + tb - 1) / tb, tb>>>(batch, N, G);
    k_edge<<<((E + 1) / 2 + tb - 1) / tb, tb>>>(ei, E, N);
    k_out<<<(N + 63) / 64, tb>>>(batch, b2, fcW, fcb, out, N, G);
}